// round 1
// baseline (speedup 1.0000x reference)
#include <cuda_runtime.h>
#include <math.h>

#define B    512
#define NP   200
#define EPG  2000
#define E_TOT (B*EPG)      // 1,024,000
#define N0   (B*NP)        // 102,400
#define HID  128
#define EMB  9
#define K1   160
#define K2   128
#define K3   103
#define N1   (B*K1)        // 81,920

// ---------------- static device scratch (no cudaMalloc allowed) --------------
__device__ float g_xe[N0*EMB];     // embedded node features (level-1 X)
__device__ float g_meanE[N0*EMB];  // level-1 neighbor means
__device__ float g_x[N0*HID];      // conv output (current level features)
__device__ float g_xp[N1*HID];     // pooled features (x_new)
__device__ float g_mean[N1*HID];   // neighbor means (level 2/3)
__device__ int   g_src[E_TOT];
__device__ int   g_dst[E_TOT];
__device__ int   g_valid[E_TOT];
__device__ float g_h[B*2*HID];     // pooled readout accumulator (x1+x2+x3)

// ---------------- init: edge copies + zero h ---------------------------------
__global__ void init_kernel(const int* __restrict__ edge_index) {
    int t = blockIdx.x * blockDim.x + threadIdx.x;
    if (t < E_TOT) {
        g_src[t]   = edge_index[t];
        g_dst[t]   = edge_index[E_TOT + t];
        g_valid[t] = 1;
    }
    if (t < B*2*HID) g_h[t] = 0.0f;
}

// ---------------- embedding gather -------------------------------------------
__global__ void gather_kernel(const int* __restrict__ node_ids,
                              const float* __restrict__ emb) {
    int t = blockIdx.x * blockDim.x + threadIdx.x;
    if (t < N0*EMB) {
        int i = t / EMB, e = t % EMB;
        g_xe[t] = emb[node_ids[i]*EMB + e];
    }
}

// ---------------- neighbor-mean aggregation (one block per graph) ------------
// Counting-sorts this graph's 2000 edges by dst (local), then warp-per-node
// accumulation of X[src] with coalesced loads.
template<int F>
__global__ void agg_kernel(int n) {
    const float* X    = (F == EMB) ? g_xe   : g_xp;
    float*       MEAN = (F == EMB) ? g_meanE : g_mean;

    __shared__ int hist[256];
    __shared__ int off[257];
    __shared__ int cur[256];
    __shared__ unsigned short ssrc[EPG];

    int b = blockIdx.x, tid = threadIdx.x;
    int ebase = b * EPG;
    int nbase = b * n;

    for (int i = tid; i < n; i += 256) hist[i] = 0;
    __syncthreads();

    for (int e = tid; e < EPG; e += 256) {
        if (g_valid[ebase + e]) {
            int dl = g_dst[ebase + e] - nbase;
            atomicAdd(&hist[dl], 1);
        }
    }
    __syncthreads();

    if (tid == 0) {
        int s = 0;
        for (int v = 0; v < n; v++) { off[v] = s; s += hist[v]; }
        off[n] = s;
    }
    __syncthreads();
    for (int i = tid; i < n; i += 256) cur[i] = off[i];
    __syncthreads();

    for (int e = tid; e < EPG; e += 256) {
        if (g_valid[ebase + e]) {
            int dl = g_dst[ebase + e] - nbase;
            int sl = g_src[ebase + e] - nbase;
            int p  = atomicAdd(&cur[dl], 1);
            ssrc[p] = (unsigned short)sl;
        }
    }
    __syncthreads();

    int warp = tid >> 5, lane = tid & 31;
    for (int v = warp; v < n; v += 8) {
        int e0 = off[v], e1 = off[v + 1];
        float inv = (e1 > e0) ? 1.0f / (float)(e1 - e0) : 0.0f;
        if (F == HID) {
            float a0 = 0.f, a1 = 0.f, a2 = 0.f, a3 = 0.f;
            for (int e = e0; e < e1; e++) {
                const float* xp = X + (size_t)(nbase + ssrc[e]) * HID;
                a0 += xp[lane];      a1 += xp[lane + 32];
                a2 += xp[lane + 64]; a3 += xp[lane + 96];
            }
            float* mp = MEAN + (size_t)(nbase + v) * HID;
            mp[lane]      = a0 * inv; mp[lane + 32] = a1 * inv;
            mp[lane + 64] = a2 * inv; mp[lane + 96] = a3 * inv;
        } else {
            if (lane < F) {
                float a = 0.f;
                for (int e = e0; e < e1; e++)
                    a += X[(size_t)(nbase + ssrc[e]) * F + lane];
                MEAN[(size_t)(nbase + v) * F + lane] = a * inv;
            }
        }
    }
}

// ---------------- conv1 GEMM: K=18 small-K, thread per (row,h) ---------------
__global__ void conv1_gemm(const float* __restrict__ w1n,
                           const float* __restrict__ w1r,
                           const float* __restrict__ b1) {
    __shared__ float wn[HID*EMB], wr[HID*EMB], bb[HID];
    int tid = threadIdx.x;
    for (int i = tid; i < HID*EMB; i += 256) { wn[i] = w1n[i]; wr[i] = w1r[i]; }
    if (tid < HID) bb[tid] = b1[tid];
    __syncthreads();

    int row = blockIdx.x * 2 + (tid >> 7);
    int h   = tid & 127;
    const float* m = g_meanE + (size_t)row * EMB;
    const float* x = g_xe    + (size_t)row * EMB;
    float acc = bb[h];
#pragma unroll
    for (int e = 0; e < EMB; e++)
        acc += m[e] * wn[h*EMB + e] + x[e] * wr[h*EMB + e];
    g_x[(size_t)row * HID + h] = fmaxf(acc, 0.0f);
}

// ---------------- SAGE GEMM: C = relu([mean|xp] @ [Wn|Wr]^T + b) --------------
// M x 128, K = 256. 128x128 tile / block, 256 threads, 8x8 microtile.
__global__ __launch_bounds__(256) void sage_gemm(const float* __restrict__ Wn,
                                                 const float* __restrict__ Wr,
                                                 const float* __restrict__ bias) {
    __shared__ float As[128][33];
    __shared__ __align__(16) float Ws[32][132];

    int tid  = threadIdx.x;
    int row0 = blockIdx.x * 128;
    int tx = tid & 15, ty = tid >> 4;
    int lk = tid & 31, li = tid >> 5;

    float acc[8][8];
#pragma unroll
    for (int r = 0; r < 8; r++)
#pragma unroll
        for (int c = 0; c < 8; c++) acc[r][c] = 0.0f;

    for (int k0 = 0; k0 < 256; k0 += 32) {
        const float* Ag = (k0 < 128) ? g_mean : g_xp;
        const float* Wg = (k0 < 128) ? Wn : Wr;
        int kg = (k0 < 128) ? k0 : (k0 - 128);

#pragma unroll
        for (int p = 0; p < 16; p++) {
            int i = li + p * 8;
            As[i][lk] = Ag[(size_t)(row0 + i) * 128 + kg + lk];
        }
#pragma unroll
        for (int p = 0; p < 16; p++) {
            int h = li + p * 8;
            Ws[lk][h] = Wg[h * 128 + kg + lk];
        }
        __syncthreads();

#pragma unroll 16
        for (int kk = 0; kk < 32; kk++) {
            float a[8];
#pragma unroll
            for (int r = 0; r < 8; r++) a[r] = As[ty*8 + r][kk];
            float4 w4a = *(const float4*)&Ws[kk][tx*8];
            float4 w4b = *(const float4*)&Ws[kk][tx*8 + 4];
            float w[8] = {w4a.x, w4a.y, w4a.z, w4a.w, w4b.x, w4b.y, w4b.z, w4b.w};
#pragma unroll
            for (int r = 0; r < 8; r++)
#pragma unroll
                for (int c = 0; c < 8; c++) acc[r][c] += a[r] * w[c];
        }
        __syncthreads();
    }

#pragma unroll
    for (int r = 0; r < 8; r++) {
        int row = row0 + ty*8 + r;
        float4 o0, o1;
        float* oo = (float*)&o0;
        float* o1p = (float*)&o1;
#pragma unroll
        for (int c = 0; c < 4; c++) oo[c]  = fmaxf(acc[r][c]     + bias[tx*8 + c],     0.0f);
#pragma unroll
        for (int c = 0; c < 4; c++) o1p[c] = fmaxf(acc[r][c + 4] + bias[tx*8 + c + 4], 0.0f);
        *(float4*)&g_x[(size_t)row * 128 + tx*8]     = o0;
        *(float4*)&g_x[(size_t)row * 128 + tx*8 + 4] = o1;
    }
}

// ---------------- topk + gain + pool + edge remap (one block per graph) ------
__global__ void topk_kernel(const float* __restrict__ pvec,
                            int n, int k, int do_remap) {
    __shared__ float s[208];
    __shared__ short newloc[208];
    __shared__ short kept[160];
    __shared__ float rn;

    int b = blockIdx.x, tid = threadIdx.x;
    int nbase = b * n;
    int warp = tid >> 5, lane = tid & 31;

    if (tid < 32) {
        float v = pvec[tid]*pvec[tid] + pvec[tid+32]*pvec[tid+32]
                + pvec[tid+64]*pvec[tid+64] + pvec[tid+96]*pvec[tid+96];
#pragma unroll
        for (int o = 16; o; o >>= 1) v += __shfl_down_sync(0xffffffffu, v, o);
        if (tid == 0) rn = 1.0f / sqrtf(v);
    }
    __syncthreads();

    // scores
    for (int v = warp; v < n; v += 8) {
        const float* xp = g_x + (size_t)(nbase + v) * HID;
        float d = xp[lane]*pvec[lane] + xp[lane+32]*pvec[lane+32]
                + xp[lane+64]*pvec[lane+64] + xp[lane+96]*pvec[lane+96];
#pragma unroll
        for (int o = 16; o; o >>= 1) d += __shfl_down_sync(0xffffffffu, d, o);
        if (lane == 0) s[v] = tanhf(d * rn);
    }
    __syncthreads();

    // rank = position in descending-score order, ties broken by lower index
    for (int v = tid; v < n; v += 256) {
        float sv = s[v];
        int r = 0;
        for (int u = 0; u < n; u++) {
            float su = s[u];
            r += (su > sv) || (su == sv && u < v);
        }
        newloc[v] = (r < k) ? (short)r : (short)-1;
        if (r < k) kept[r] = (short)v;
    }
    __syncthreads();

    if (tid < 128) {
        // x_new (gain-multiplied) + global max/mean pool, dim per thread
        int d = tid;
        int obase = b * k;
        float mx = -INFINITY, sm = 0.0f;
        for (int r = 0; r < k; r++) {
            int v = kept[r];
            float val = g_x[(size_t)(nbase + v) * HID + d] * s[v];
            g_xp[(size_t)(obase + r) * HID + d] = val;
            mx = fmaxf(mx, val);
            sm += val;
        }
        g_h[b*256 + d]       += mx;
        g_h[b*256 + 128 + d] += sm / (float)k;
    } else if (do_remap) {
        for (int e = b*EPG + (tid - 128); e < (b + 1)*EPG; e += 128) {
            int val = g_valid[e];
            int ns = -1, nd = -1;
            if (val) {
                ns = newloc[g_src[e] - nbase];
                nd = newloc[g_dst[e] - nbase];
            }
            int ok = val && (ns >= 0) && (nd >= 0);
            g_src[e]   = b*k + (ns >= 0 ? ns : 0);
            g_dst[e]   = b*k + (nd >= 0 ? nd : 0);
            g_valid[e] = ok;
        }
    }
}

// ---------------- final MLP head: 256 -> 128 -> 64 -> 1 (sigmoid) ------------
__global__ void mlp_kernel(const float* __restrict__ lw1, const float* __restrict__ lb1,
                           const float* __restrict__ lw2, const float* __restrict__ lb2,
                           const float* __restrict__ lw3, const float* __restrict__ lb3,
                           float* __restrict__ out) {
    __shared__ float hs[8][256];
    __shared__ float h1[8][128];
    __shared__ float h2[8][64];
    int tid = threadIdx.x;           // 128 threads
    int b0  = blockIdx.x * 8;

    for (int idx = tid; idx < 8*256; idx += 128) {
        int r = idx >> 8, c = idx & 255;
        hs[r][c] = g_h[(b0 + r)*256 + c];
    }
    __syncthreads();

    {   // layer 1: all 128 threads, one output col each, 8 rows
        float acc[8];
        float bb = lb1[tid];
#pragma unroll
        for (int r = 0; r < 8; r++) acc[r] = bb;
        for (int kk = 0; kk < 256; kk++) {
            float w = lw1[tid*256 + kk];
#pragma unroll
            for (int r = 0; r < 8; r++) acc[r] += hs[r][kk] * w;
        }
#pragma unroll
        for (int r = 0; r < 8; r++) h1[r][tid] = fmaxf(acc[r], 0.0f);
    }
    __syncthreads();

    if (tid < 64) { // layer 2
        float acc[8];
        float bb = lb2[tid];
#pragma unroll
        for (int r = 0; r < 8; r++) acc[r] = bb;
        for (int kk = 0; kk < 128; kk++) {
            float w = lw2[tid*128 + kk];
#pragma unroll
            for (int r = 0; r < 8; r++) acc[r] += h1[r][kk] * w;
        }
#pragma unroll
        for (int r = 0; r < 8; r++) h2[r][tid] = fmaxf(acc[r], 0.0f);
    }
    __syncthreads();

    if (tid < 8) { // layer 3 + sigmoid
        float acc = lb3[0];
        for (int kk = 0; kk < 64; kk++) acc += h2[tid][kk] * lw3[kk];
        out[b0 + tid] = 1.0f / (1.0f + expf(-acc));
    }
}

// ---------------- launch ------------------------------------------------------
extern "C" void kernel_launch(void* const* d_in, const int* in_sizes, int n_in,
                              void* d_out, int out_size) {
    const int*   node_ids   = (const int*)d_in[0];
    const int*   edge_index = (const int*)d_in[1];
    // d_in[2] = batch (unused by reference)
    const float* emb  = (const float*)d_in[3];
    const float* w1n  = (const float*)d_in[4];
    const float* w1r  = (const float*)d_in[5];
    const float* b1   = (const float*)d_in[6];
    const float* w2n  = (const float*)d_in[7];
    const float* w2r  = (const float*)d_in[8];
    const float* b2   = (const float*)d_in[9];
    const float* w3n  = (const float*)d_in[10];
    const float* w3r  = (const float*)d_in[11];
    const float* b3   = (const float*)d_in[12];
    const float* p1   = (const float*)d_in[13];
    const float* p2   = (const float*)d_in[14];
    const float* p3   = (const float*)d_in[15];
    const float* lw1  = (const float*)d_in[16];
    const float* lb1  = (const float*)d_in[17];
    const float* lw2  = (const float*)d_in[18];
    const float* lb2  = (const float*)d_in[19];
    const float* lw3  = (const float*)d_in[20];
    const float* lb3  = (const float*)d_in[21];
    float* out = (float*)d_out;

    init_kernel<<<(E_TOT + 255)/256, 256>>>(edge_index);
    gather_kernel<<<(N0*EMB + 255)/256, 256>>>(node_ids, emb);

    // level 1
    agg_kernel<EMB><<<B, 256>>>(NP);
    conv1_gemm<<<N0/2, 256>>>(w1n, w1r, b1);
    topk_kernel<<<B, 256>>>(p1, NP, K1, 1);

    // level 2
    agg_kernel<HID><<<B, 256>>>(K1);
    sage_gemm<<<(B*K1)/128, 256>>>(w2n, w2r, b2);
    topk_kernel<<<B, 256>>>(p2, K1, K2, 1);

    // level 3
    agg_kernel<HID><<<B, 256>>>(K2);
    sage_gemm<<<(B*K2)/128, 256>>>(w3n, w3r, b3);
    topk_kernel<<<B, 256>>>(p3, K2, K3, 0);

    mlp_kernel<<<B/8, 128>>>(lw1, lb1, lw2, lb2, lw3, lb3, out);
}

// round 2
// speedup vs baseline: 1.2307x; 1.2307x over previous
#include <cuda_runtime.h>
#include <math.h>
#include <stdint.h>

#define B    512
#define NP   200
#define EPG  2000
#define E_TOT (B*EPG)      // 1,024,000
#define N0   (B*NP)        // 102,400
#define HID  128
#define EMB  9
#define K1   160
#define K2   128
#define K3   103
#define N1   (B*K1)        // 81,920

// ---------------- static device scratch (no cudaMalloc allowed) --------------
__device__ float g_xe[N0*EMB];     // embedded node features (level-1 X)
__device__ float g_meanE[N0*EMB];  // level-1 neighbor means
__device__ float g_x[N0*HID];      // conv output (current level features)
__device__ float g_xp[N1*HID];     // pooled features (x_new)
__device__ float g_mean[N1*HID];   // neighbor means (level 2/3)
__device__ int   g_src[E_TOT];
__device__ int   g_dst[E_TOT];
__device__ int   g_valid[E_TOT];
__device__ float g_h[B*2*HID];     // pooled readout accumulator (x1+x2+x3)

// ---------------- init: edge copies + zero h ---------------------------------
__global__ void init_kernel(const int* __restrict__ edge_index) {
    int t = blockIdx.x * blockDim.x + threadIdx.x;
    if (t < E_TOT) {
        g_src[t]   = edge_index[t];
        g_dst[t]   = edge_index[E_TOT + t];
        g_valid[t] = 1;
    }
    if (t < B*2*HID) g_h[t] = 0.0f;
}

// ---------------- embedding gather -------------------------------------------
__global__ void gather_kernel(const int* __restrict__ node_ids,
                              const float* __restrict__ emb) {
    int t = blockIdx.x * blockDim.x + threadIdx.x;
    if (t < N0*EMB) {
        int i = t / EMB, e = t % EMB;
        g_xe[t] = emb[node_ids[i]*EMB + e];
    }
}

// ---------------- neighbor-mean aggregation (one block per graph) ------------
template<int F>
__global__ void agg_kernel(int n) {
    const float* X    = (F == EMB) ? g_xe   : g_xp;
    float*       MEAN = (F == EMB) ? g_meanE : g_mean;

    __shared__ int hist[256];
    __shared__ int off[257];
    __shared__ int cur[256];
    __shared__ unsigned short ssrc[EPG];

    int b = blockIdx.x, tid = threadIdx.x;
    int ebase = b * EPG;
    int nbase = b * n;

    for (int i = tid; i < n; i += 256) hist[i] = 0;
    __syncthreads();

    for (int e = tid; e < EPG; e += 256) {
        if (g_valid[ebase + e]) {
            int dl = g_dst[ebase + e] - nbase;
            atomicAdd(&hist[dl], 1);
        }
    }
    __syncthreads();

    if (tid == 0) {
        int s = 0;
        for (int v = 0; v < n; v++) { off[v] = s; s += hist[v]; }
        off[n] = s;
    }
    __syncthreads();
    for (int i = tid; i < n; i += 256) cur[i] = off[i];
    __syncthreads();

    for (int e = tid; e < EPG; e += 256) {
        if (g_valid[ebase + e]) {
            int dl = g_dst[ebase + e] - nbase;
            int sl = g_src[ebase + e] - nbase;
            int p  = atomicAdd(&cur[dl], 1);
            ssrc[p] = (unsigned short)sl;
        }
    }
    __syncthreads();

    int warp = tid >> 5, lane = tid & 31;
    for (int v = warp; v < n; v += 8) {
        int e0 = off[v], e1 = off[v + 1];
        float inv = (e1 > e0) ? 1.0f / (float)(e1 - e0) : 0.0f;
        if (F == HID) {
            float a0 = 0.f, a1 = 0.f, a2 = 0.f, a3 = 0.f;
            for (int e = e0; e < e1; e++) {
                const float* xp = X + (size_t)(nbase + ssrc[e]) * HID;
                a0 += xp[lane];      a1 += xp[lane + 32];
                a2 += xp[lane + 64]; a3 += xp[lane + 96];
            }
            float* mp = MEAN + (size_t)(nbase + v) * HID;
            mp[lane]      = a0 * inv; mp[lane + 32] = a1 * inv;
            mp[lane + 64] = a2 * inv; mp[lane + 96] = a3 * inv;
        } else {
            if (lane < F) {
                float a = 0.f;
                for (int e = e0; e < e1; e++)
                    a += X[(size_t)(nbase + ssrc[e]) * F + lane];
                MEAN[(size_t)(nbase + v) * F + lane] = a * inv;
            }
        }
    }
}

// ---------------- conv1: K=18, weights in registers, broadcast features ------
// 256 threads: thread owns output column h = tid&127; processes 128 rows/block.
__global__ __launch_bounds__(256) void conv1_kernel(
        const float* __restrict__ w1n,
        const float* __restrict__ w1r,
        const float* __restrict__ b1) {
    int tid = threadIdx.x;
    int h   = tid & 127;

    float wn[EMB], wr[EMB];
#pragma unroll
    for (int e = 0; e < EMB; e++) { wn[e] = w1n[h*EMB + e]; wr[e] = w1r[h*EMB + e]; }
    float bias = b1[h];

    int row0 = blockIdx.x * 128;
    for (int r = (tid >> 7); r < 128; r += 2) {
        int row = row0 + r;
        const float* m = g_meanE + (size_t)row * EMB;
        const float* x = g_xe    + (size_t)row * EMB;
        float acc = bias;
#pragma unroll
        for (int e = 0; e < EMB; e++) acc += m[e] * wn[e];
#pragma unroll
        for (int e = 0; e < EMB; e++) acc += x[e] * wr[e];
        g_x[(size_t)row * HID + h] = fmaxf(acc, 0.0f);
    }
}

// ---------------- tf32 tensor-core SAGE GEMM ---------------------------------
// C = relu([mean | xp] @ [Wn | Wr]^T + b),  M x 128, K = 256 (tf32 HMMA).
__device__ __forceinline__ uint32_t f2tf32(float f) {
    uint32_t u;
    asm("cvt.rna.tf32.f32 %0, %1;" : "=r"(u) : "f"(f));
    return u;
}
__device__ __forceinline__ void mma_tf32(float c[4], uint32_t a0, uint32_t a1,
                                         uint32_t a2, uint32_t a3,
                                         uint32_t b0, uint32_t b1) {
    asm volatile(
        "mma.sync.aligned.m16n8k8.row.col.f32.tf32.tf32.f32 "
        "{%0,%1,%2,%3}, {%4,%5,%6,%7}, {%8,%9}, {%0,%1,%2,%3};"
        : "+f"(c[0]), "+f"(c[1]), "+f"(c[2]), "+f"(c[3])
        : "r"(a0), "r"(a1), "r"(a2), "r"(a3), "r"(b0), "r"(b1));
}

__global__ __launch_bounds__(256) void sage_gemm_tf32(
        const float* __restrict__ Wn,
        const float* __restrict__ Wr,
        const float* __restrict__ bias) {
    __shared__ uint32_t As[128][36];   // A tile (tf32), 32 k-cols, pad 4
    __shared__ uint32_t Ws[128][36];   // W tile (tf32), row = n, col = k
    __shared__ float    bb[128];

    int tid  = threadIdx.x;
    int lane = tid & 31;
    int wid  = tid >> 5;               // 8 warps
    int wm   = wid & 3;                // warp M index (4)  -> 32 rows
    int wn   = wid >> 2;               // warp N index (2)  -> 64 cols
    int row0 = blockIdx.x * 128;

    if (tid < 128) bb[tid] = bias[tid];

    float acc[2][8][4];
#pragma unroll
    for (int mt = 0; mt < 2; mt++)
#pragma unroll
        for (int nt = 0; nt < 8; nt++)
#pragma unroll
            for (int i = 0; i < 4; i++) acc[mt][nt][i] = 0.0f;

    for (int kc = 0; kc < 256; kc += 32) {
        const float* Ag = (kc < 128) ? g_mean : g_xp;
        const float* Wg = (kc < 128) ? Wn : Wr;
        int kg = kc & 127;

        // stage A (128x32) and W (128x32), tf32-rounded
#pragma unroll
        for (int p = 0; p < 16; p++) {
            int idx = p * 256 + tid;
            int r = idx >> 5, c = idx & 31;
            As[r][c] = f2tf32(Ag[(size_t)(row0 + r) * 128 + kg + c]);
            Ws[r][c] = f2tf32(Wg[r * 128 + kg + c]);
        }
        __syncthreads();

#pragma unroll
        for (int ks = 0; ks < 32; ks += 8) {
            uint32_t a[2][4];
#pragma unroll
            for (int mt = 0; mt < 2; mt++) {
                int r = wm * 32 + mt * 16 + (lane >> 2);
                int c = ks + (lane & 3);
                a[mt][0] = As[r][c];
                a[mt][1] = As[r + 8][c];
                a[mt][2] = As[r][c + 4];
                a[mt][3] = As[r + 8][c + 4];
            }
#pragma unroll
            for (int nt = 0; nt < 8; nt++) {
                int n = wn * 64 + nt * 8 + (lane >> 2);
                int c = ks + (lane & 3);
                uint32_t b0 = Ws[n][c];
                uint32_t b1 = Ws[n][c + 4];
                mma_tf32(acc[0][nt], a[0][0], a[0][1], a[0][2], a[0][3], b0, b1);
                mma_tf32(acc[1][nt], a[1][0], a[1][1], a[1][2], a[1][3], b0, b1);
            }
        }
        __syncthreads();
    }

    // epilogue: bias + relu, c0/c1 are adjacent columns -> float2 stores
#pragma unroll
    for (int mt = 0; mt < 2; mt++) {
#pragma unroll
        for (int nt = 0; nt < 8; nt++) {
            int col = wn * 64 + nt * 8 + 2 * (lane & 3);
            int r0  = row0 + wm * 32 + mt * 16 + (lane >> 2);
            float2 v0, v1;
            v0.x = fmaxf(acc[mt][nt][0] + bb[col],     0.0f);
            v0.y = fmaxf(acc[mt][nt][1] + bb[col + 1], 0.0f);
            v1.x = fmaxf(acc[mt][nt][2] + bb[col],     0.0f);
            v1.y = fmaxf(acc[mt][nt][3] + bb[col + 1], 0.0f);
            *(float2*)&g_x[(size_t)r0 * 128 + col]       = v0;
            *(float2*)&g_x[(size_t)(r0 + 8) * 128 + col] = v1;
        }
    }
}

// ---------------- topk + gain + pool + edge remap (one block per graph) ------
__global__ void topk_kernel(const float* __restrict__ pvec,
                            int n, int k, int do_remap) {
    __shared__ float s[208];
    __shared__ short newloc[208];
    __shared__ short kept[160];
    __shared__ float rn;

    int b = blockIdx.x, tid = threadIdx.x;
    int nbase = b * n;
    int warp = tid >> 5, lane = tid & 31;

    if (tid < 32) {
        float v = pvec[tid]*pvec[tid] + pvec[tid+32]*pvec[tid+32]
                + pvec[tid+64]*pvec[tid+64] + pvec[tid+96]*pvec[tid+96];
#pragma unroll
        for (int o = 16; o; o >>= 1) v += __shfl_down_sync(0xffffffffu, v, o);
        if (tid == 0) rn = 1.0f / sqrtf(v);
    }
    __syncthreads();

    for (int v = warp; v < n; v += 8) {
        const float* xp = g_x + (size_t)(nbase + v) * HID;
        float d = xp[lane]*pvec[lane] + xp[lane+32]*pvec[lane+32]
                + xp[lane+64]*pvec[lane+64] + xp[lane+96]*pvec[lane+96];
#pragma unroll
        for (int o = 16; o; o >>= 1) d += __shfl_down_sync(0xffffffffu, d, o);
        if (lane == 0) s[v] = tanhf(d * rn);
    }
    __syncthreads();

    for (int v = tid; v < n; v += 256) {
        float sv = s[v];
        int r = 0;
        for (int u = 0; u < n; u++) {
            float su = s[u];
            r += (su > sv) || (su == sv && u < v);
        }
        newloc[v] = (r < k) ? (short)r : (short)-1;
        if (r < k) kept[r] = (short)v;
    }
    __syncthreads();

    if (tid < 128) {
        int d = tid;
        int obase = b * k;
        float mx = -INFINITY, sm = 0.0f;
        for (int r = 0; r < k; r++) {
            int v = kept[r];
            float val = g_x[(size_t)(nbase + v) * HID + d] * s[v];
            g_xp[(size_t)(obase + r) * HID + d] = val;
            mx = fmaxf(mx, val);
            sm += val;
        }
        g_h[b*256 + d]       += mx;
        g_h[b*256 + 128 + d] += sm / (float)k;
    } else if (do_remap) {
        for (int e = b*EPG + (tid - 128); e < (b + 1)*EPG; e += 128) {
            int val = g_valid[e];
            int ns = -1, nd = -1;
            if (val) {
                ns = newloc[g_src[e] - nbase];
                nd = newloc[g_dst[e] - nbase];
            }
            int ok = val && (ns >= 0) && (nd >= 0);
            g_src[e]   = b*k + (ns >= 0 ? ns : 0);
            g_dst[e]   = b*k + (nd >= 0 ? nd : 0);
            g_valid[e] = ok;
        }
    }
}

// ---------------- final MLP head: 256 -> 128 -> 64 -> 1 (sigmoid) ------------
__global__ void mlp_kernel(const float* __restrict__ lw1, const float* __restrict__ lb1,
                           const float* __restrict__ lw2, const float* __restrict__ lb2,
                           const float* __restrict__ lw3, const float* __restrict__ lb3,
                           float* __restrict__ out) {
    __shared__ float hs[8][256];
    __shared__ float h1[8][128];
    __shared__ float h2[8][64];
    int tid = threadIdx.x;           // 128 threads
    int b0  = blockIdx.x * 8;

    for (int idx = tid; idx < 8*256; idx += 128) {
        int r = idx >> 8, c = idx & 255;
        hs[r][c] = g_h[(b0 + r)*256 + c];
    }
    __syncthreads();

    {
        float acc[8];
        float bbv = lb1[tid];
#pragma unroll
        for (int r = 0; r < 8; r++) acc[r] = bbv;
        for (int kk = 0; kk < 256; kk++) {
            float w = lw1[tid*256 + kk];
#pragma unroll
            for (int r = 0; r < 8; r++) acc[r] += hs[r][kk] * w;
        }
#pragma unroll
        for (int r = 0; r < 8; r++) h1[r][tid] = fmaxf(acc[r], 0.0f);
    }
    __syncthreads();

    if (tid < 64) {
        float acc[8];
        float bbv = lb2[tid];
#pragma unroll
        for (int r = 0; r < 8; r++) acc[r] = bbv;
        for (int kk = 0; kk < 128; kk++) {
            float w = lw2[tid*128 + kk];
#pragma unroll
            for (int r = 0; r < 8; r++) acc[r] += h1[r][kk] * w;
        }
#pragma unroll
        for (int r = 0; r < 8; r++) h2[r][tid] = fmaxf(acc[r], 0.0f);
    }
    __syncthreads();

    if (tid < 8) {
        float acc = lb3[0];
        for (int kk = 0; kk < 64; kk++) acc += h2[tid][kk] * lw3[kk];
        out[b0 + tid] = 1.0f / (1.0f + expf(-acc));
    }
}

// ---------------- launch ------------------------------------------------------
extern "C" void kernel_launch(void* const* d_in, const int* in_sizes, int n_in,
                              void* d_out, int out_size) {
    const int*   node_ids   = (const int*)d_in[0];
    const int*   edge_index = (const int*)d_in[1];
    const float* emb  = (const float*)d_in[3];
    const float* w1n  = (const float*)d_in[4];
    const float* w1r  = (const float*)d_in[5];
    const float* b1   = (const float*)d_in[6];
    const float* w2n  = (const float*)d_in[7];
    const float* w2r  = (const float*)d_in[8];
    const float* b2   = (const float*)d_in[9];
    const float* w3n  = (const float*)d_in[10];
    const float* w3r  = (const float*)d_in[11];
    const float* b3   = (const float*)d_in[12];
    const float* p1   = (const float*)d_in[13];
    const float* p2   = (const float*)d_in[14];
    const float* p3   = (const float*)d_in[15];
    const float* lw1  = (const float*)d_in[16];
    const float* lb1  = (const float*)d_in[17];
    const float* lw2  = (const float*)d_in[18];
    const float* lb2  = (const float*)d_in[19];
    const float* lw3  = (const float*)d_in[20];
    const float* lb3  = (const float*)d_in[21];
    float* out = (float*)d_out;

    init_kernel<<<(E_TOT + 255)/256, 256>>>(edge_index);
    gather_kernel<<<(N0*EMB + 255)/256, 256>>>(node_ids, emb);

    // level 1
    agg_kernel<EMB><<<B, 256>>>(NP);
    conv1_kernel<<<N0/128, 256>>>(w1n, w1r, b1);
    topk_kernel<<<B, 256>>>(p1, NP, K1, 1);

    // level 2
    agg_kernel<HID><<<B, 256>>>(K1);
    sage_gemm_tf32<<<(B*K1)/128, 256>>>(w2n, w2r, b2);
    topk_kernel<<<B, 256>>>(p2, K1, K2, 1);

    // level 3
    agg_kernel<HID><<<B, 256>>>(K2);
    sage_gemm_tf32<<<(B*K2)/128, 256>>>(w3n, w3r, b3);
    topk_kernel<<<B, 256>>>(p3, K2, K3, 0);

    mlp_kernel<<<B/8, 128>>>(lw1, lb1, lw2, lb2, lw3, lb3, out);
}

// round 3
// speedup vs baseline: 1.3485x; 1.0957x over previous
#include <cuda_runtime.h>
#include <math.h>
#include <stdint.h>

#define B    512
#define NP   200
#define EPG  2000
#define E_TOT (B*EPG)      // 1,024,000
#define N0   (B*NP)        // 102,400
#define HID  128
#define EMB  9
#define K1   160
#define K2   128
#define K3   103
#define N1   (B*K1)        // 81,920

// ---------------- static device scratch (no cudaMalloc allowed) --------------
__device__ float g_xe[N0*EMB];     // embedded node features (level-1 X)
__device__ float g_meanE[N0*EMB];  // level-1 neighbor means
__device__ float g_x[N0*HID];      // conv output (current level features)
__device__ float g_xp[N1*HID];     // pooled features (x_new)
__device__ float g_mean[N1*HID];   // neighbor means (level 2/3)
__device__ float g_sdot[N0];       // fused score dot (x_row . p)
__device__ int   g_src[E_TOT];
__device__ int   g_dst[E_TOT];
__device__ int   g_valid[E_TOT];
__device__ float g_h[B*2*HID];     // pooled readout accumulator (x1+x2+x3)

// ---------------- init: edge copies + zero h ---------------------------------
__global__ void init_kernel(const int* __restrict__ edge_index) {
    int t = blockIdx.x * blockDim.x + threadIdx.x;
    if (t < E_TOT) {
        g_src[t]   = edge_index[t];
        g_dst[t]   = edge_index[E_TOT + t];
        g_valid[t] = 1;
    }
    if (t < B*2*HID) g_h[t] = 0.0f;
}

// ---------------- embedding gather -------------------------------------------
__global__ void gather_kernel(const int* __restrict__ node_ids,
                              const float* __restrict__ emb) {
    int t = blockIdx.x * blockDim.x + threadIdx.x;
    if (t < N0*EMB) {
        int i = t / EMB, e = t % EMB;
        g_xe[t] = emb[node_ids[i]*EMB + e];
    }
}

// ---------------- neighbor-mean aggregation (one block per graph) ------------
template<int F>
__global__ void agg_kernel(int n) {
    const float* X    = (F == EMB) ? g_xe   : g_xp;
    float*       MEAN = (F == EMB) ? g_meanE : g_mean;

    __shared__ int hist[256];
    __shared__ int off[257];
    __shared__ int cur[256];
    __shared__ unsigned short ssrc[EPG];

    int b = blockIdx.x, tid = threadIdx.x;
    int ebase = b * EPG;
    int nbase = b * n;

    for (int i = tid; i < n; i += 256) hist[i] = 0;
    __syncthreads();

    for (int e = tid; e < EPG; e += 256) {
        if (g_valid[ebase + e]) {
            int dl = g_dst[ebase + e] - nbase;
            atomicAdd(&hist[dl], 1);
        }
    }
    __syncthreads();

    if (tid == 0) {
        int s = 0;
        for (int v = 0; v < n; v++) { off[v] = s; s += hist[v]; }
        off[n] = s;
    }
    __syncthreads();
    for (int i = tid; i < n; i += 256) cur[i] = off[i];
    __syncthreads();

    for (int e = tid; e < EPG; e += 256) {
        if (g_valid[ebase + e]) {
            int dl = g_dst[ebase + e] - nbase;
            int sl = g_src[ebase + e] - nbase;
            int p  = atomicAdd(&cur[dl], 1);
            ssrc[p] = (unsigned short)sl;
        }
    }
    __syncthreads();

    int warp = tid >> 5, lane = tid & 31;
    for (int v = warp; v < n; v += 8) {
        int e0 = off[v], e1 = off[v + 1];
        float inv = (e1 > e0) ? 1.0f / (float)(e1 - e0) : 0.0f;
        if (F == HID) {
            float a0 = 0.f, a1 = 0.f, a2 = 0.f, a3 = 0.f;
            for (int e = e0; e < e1; e++) {
                const float* xp = X + (size_t)(nbase + ssrc[e]) * HID;
                a0 += xp[lane];      a1 += xp[lane + 32];
                a2 += xp[lane + 64]; a3 += xp[lane + 96];
            }
            float* mp = MEAN + (size_t)(nbase + v) * HID;
            mp[lane]      = a0 * inv; mp[lane + 32] = a1 * inv;
            mp[lane + 64] = a2 * inv; mp[lane + 96] = a3 * inv;
        } else {
            if (lane < F) {
                float a = 0.f;
                for (int e = e0; e < e1; e++)
                    a += X[(size_t)(nbase + ssrc[e]) * F + lane];
                MEAN[(size_t)(nbase + v) * F + lane] = a * inv;
            }
        }
    }
}

// ---------------- tf32 mma primitive -----------------------------------------
__device__ __forceinline__ void mma_tf32(float c[4], uint32_t a0, uint32_t a1,
                                         uint32_t a2, uint32_t a3,
                                         uint32_t b0, uint32_t b1) {
    asm volatile(
        "mma.sync.aligned.m16n8k8.row.col.f32.tf32.tf32.f32 "
        "{%0,%1,%2,%3}, {%4,%5,%6,%7}, {%8,%9}, {%0,%1,%2,%3};"
        : "+f"(c[0]), "+f"(c[1]), "+f"(c[2]), "+f"(c[3])
        : "r"(a0), "r"(a1), "r"(a2), "r"(a3), "r"(b0), "r"(b1));
}

// Shared epilogue: bias + relu + store to g_x, fused score-dot to g_sdot.
// Thread layout: wm = warp M (4), wn_ = warp N (2); rows rr = wm*32+mt*16+(lane>>2)
// and rr+8; cols col = wn_*64+nt*8+2*(lane&3), col+1.
__device__ __forceinline__ void gemm_epilogue(
        float acc[2][8][4], const float* bb, const float* ps, float* sdot,
        int row0, int wm, int wn_, int lane) {
#pragma unroll
    for (int mt = 0; mt < 2; mt++) {
        float pd0 = 0.0f, pd1 = 0.0f;
        int rr = wm * 32 + mt * 16 + (lane >> 2);
#pragma unroll
        for (int nt = 0; nt < 8; nt++) {
            int col = wn_ * 64 + nt * 8 + 2 * (lane & 3);
            float v00 = fmaxf(acc[mt][nt][0] + bb[col],     0.0f);
            float v01 = fmaxf(acc[mt][nt][1] + bb[col + 1], 0.0f);
            float v10 = fmaxf(acc[mt][nt][2] + bb[col],     0.0f);
            float v11 = fmaxf(acc[mt][nt][3] + bb[col + 1], 0.0f);
            float2 w0 = make_float2(v00, v01);
            float2 w1 = make_float2(v10, v11);
            *(float2*)&g_x[(size_t)(row0 + rr) * 128 + col]     = w0;
            *(float2*)&g_x[(size_t)(row0 + rr + 8) * 128 + col] = w1;
            pd0 += v00 * ps[col] + v01 * ps[col + 1];
            pd1 += v10 * ps[col] + v11 * ps[col + 1];
        }
        pd0 += __shfl_xor_sync(0xffffffffu, pd0, 1);
        pd0 += __shfl_xor_sync(0xffffffffu, pd0, 2);
        pd1 += __shfl_xor_sync(0xffffffffu, pd1, 1);
        pd1 += __shfl_xor_sync(0xffffffffu, pd1, 2);
        if ((lane & 3) == 0) {
            atomicAdd(&sdot[rr], pd0);
            atomicAdd(&sdot[rr + 8], pd1);
        }
    }
}

// ---------------- SAGE GEMM: C = relu([mean|xp] @ [Wn|Wr]^T + b) -------------
// M x 128, K = 256. tf32 mma, raw-bit truncation, float4 staging, fused score.
__global__ __launch_bounds__(256) void sage_gemm(
        const float* __restrict__ Wn,
        const float* __restrict__ Wr,
        const float* __restrict__ bias,
        const float* __restrict__ pvec) {
    __shared__ float As[128][36];
    __shared__ float Ws[128][36];
    __shared__ float bb[128];
    __shared__ float ps[128];
    __shared__ float sdot[128];

    int tid  = threadIdx.x;
    int lane = tid & 31;
    int wid  = tid >> 5;
    int wm   = wid & 3;
    int wn_  = wid >> 2;
    int row0 = blockIdx.x * 128;

    if (tid < 128) { bb[tid] = bias[tid]; ps[tid] = pvec[tid]; sdot[tid] = 0.0f; }

    float acc[2][8][4];
#pragma unroll
    for (int mt = 0; mt < 2; mt++)
#pragma unroll
        for (int nt = 0; nt < 8; nt++)
#pragma unroll
            for (int i = 0; i < 4; i++) acc[mt][nt][i] = 0.0f;

    for (int kc = 0; kc < 256; kc += 32) {
        const float* Ag = (kc < 128) ? g_mean : g_xp;
        const float* Wg = (kc < 128) ? Wn : Wr;
        int kg = kc & 127;

        // float4 staging: 128 rows x 8 float4 each for A and W
#pragma unroll
        for (int t = 0; t < 4; t++) {
            int e = t * 256 + tid;
            int r = e >> 3, q = e & 7;
            float4 av = *(const float4*)&Ag[(size_t)(row0 + r) * 128 + kg + q * 4];
            *(float4*)&As[r][q * 4] = av;
            float4 wv = *(const float4*)&Wg[r * 128 + kg + q * 4];
            *(float4*)&Ws[r][q * 4] = wv;
        }
        __syncthreads();

#pragma unroll
        for (int ks = 0; ks < 32; ks += 8) {
            uint32_t a[2][4];
#pragma unroll
            for (int mt = 0; mt < 2; mt++) {
                int r = wm * 32 + mt * 16 + (lane >> 2);
                int c = ks + (lane & 3);
                a[mt][0] = __float_as_uint(As[r][c]);
                a[mt][1] = __float_as_uint(As[r + 8][c]);
                a[mt][2] = __float_as_uint(As[r][c + 4]);
                a[mt][3] = __float_as_uint(As[r + 8][c + 4]);
            }
#pragma unroll
            for (int nt = 0; nt < 8; nt++) {
                int n = wn_ * 64 + nt * 8 + (lane >> 2);
                int c = ks + (lane & 3);
                uint32_t b0 = __float_as_uint(Ws[n][c]);
                uint32_t b1 = __float_as_uint(Ws[n][c + 4]);
                mma_tf32(acc[0][nt], a[0][0], a[0][1], a[0][2], a[0][3], b0, b1);
                mma_tf32(acc[1][nt], a[1][0], a[1][1], a[1][2], a[1][3], b0, b1);
            }
        }
        __syncthreads();
    }

    gemm_epilogue(acc, bb, ps, sdot, row0, wm, wn_, lane);
    __syncthreads();
    if (tid < 128) g_sdot[row0 + tid] = sdot[tid];
}

// ---------------- conv1 GEMM: K=18 (padded 24), same mma structure -----------
__global__ __launch_bounds__(256) void conv1_gemm(
        const float* __restrict__ w1n,
        const float* __restrict__ w1r,
        const float* __restrict__ b1,
        const float* __restrict__ pvec) {
    __shared__ float As[128][36];
    __shared__ float Ws[128][36];
    __shared__ float bb[128];
    __shared__ float ps[128];
    __shared__ float sdot[128];

    int tid  = threadIdx.x;
    int lane = tid & 31;
    int wid  = tid >> 5;
    int wm   = wid & 3;
    int wn_  = wid >> 2;
    int row0 = blockIdx.x * 128;

    if (tid < 128) { bb[tid] = b1[tid]; ps[tid] = pvec[tid]; sdot[tid] = 0.0f; }

    // stage A = [meanE | xe | 0-pad], W = [w1n | w1r | 0-pad], 128 x 32
#pragma unroll
    for (int p = 0; p < 16; p++) {
        int idx = p * 256 + tid;
        int r = idx >> 5, c = idx & 31;
        float av = 0.0f, wv = 0.0f;
        if (c < EMB) {
            av = g_meanE[(size_t)(row0 + r) * EMB + c];
            wv = w1n[r * EMB + c];
        } else if (c < 2*EMB) {
            av = g_xe[(size_t)(row0 + r) * EMB + (c - EMB)];
            wv = w1r[r * EMB + (c - EMB)];
        }
        As[r][c] = av;
        Ws[r][c] = wv;
    }
    __syncthreads();

    float acc[2][8][4];
#pragma unroll
    for (int mt = 0; mt < 2; mt++)
#pragma unroll
        for (int nt = 0; nt < 8; nt++)
#pragma unroll
            for (int i = 0; i < 4; i++) acc[mt][nt][i] = 0.0f;

#pragma unroll
    for (int ks = 0; ks < 24; ks += 8) {   // K = 18 real, padded to 24
        uint32_t a[2][4];
#pragma unroll
        for (int mt = 0; mt < 2; mt++) {
            int r = wm * 32 + mt * 16 + (lane >> 2);
            int c = ks + (lane & 3);
            a[mt][0] = __float_as_uint(As[r][c]);
            a[mt][1] = __float_as_uint(As[r + 8][c]);
            a[mt][2] = __float_as_uint(As[r][c + 4]);
            a[mt][3] = __float_as_uint(As[r + 8][c + 4]);
        }
#pragma unroll
        for (int nt = 0; nt < 8; nt++) {
            int n = wn_ * 64 + nt * 8 + (lane >> 2);
            int c = ks + (lane & 3);
            uint32_t b0 = __float_as_uint(Ws[n][c]);
            uint32_t b1 = __float_as_uint(Ws[n][c + 4]);
            mma_tf32(acc[0][nt], a[0][0], a[0][1], a[0][2], a[0][3], b0, b1);
            mma_tf32(acc[1][nt], a[1][0], a[1][1], a[1][2], a[1][3], b0, b1);
        }
    }
    __syncthreads();

    gemm_epilogue(acc, bb, ps, sdot, row0, wm, wn_, lane);
    __syncthreads();
    if (tid < 128) g_sdot[row0 + tid] = sdot[tid];
}

// ---------------- topk + gain + pool + edge remap (one block per graph) ------
__global__ void topk_kernel(const float* __restrict__ pvec,
                            int n, int k, int do_remap) {
    __shared__ float s[208];
    __shared__ short newloc[208];
    __shared__ short kept[160];
    __shared__ float rn;

    int b = blockIdx.x, tid = threadIdx.x;
    int nbase = b * n;

    if (tid < 32) {
        float v = pvec[tid]*pvec[tid] + pvec[tid+32]*pvec[tid+32]
                + pvec[tid+64]*pvec[tid+64] + pvec[tid+96]*pvec[tid+96];
#pragma unroll
        for (int o = 16; o; o >>= 1) v += __shfl_down_sync(0xffffffffu, v, o);
        if (tid == 0) rn = 1.0f / sqrtf(v);
    }
    __syncthreads();

    // scores from fused epilogue dot
    for (int v = tid; v < n; v += 256)
        s[v] = tanhf(g_sdot[nbase + v] * rn);
    __syncthreads();

    // rank = position in descending-score order, ties broken by lower index
    for (int v = tid; v < n; v += 256) {
        float sv = s[v];
        int r = 0;
        for (int u = 0; u < n; u++) {
            float su = s[u];
            r += (su > sv) || (su == sv && u < v);
        }
        newloc[v] = (r < k) ? (short)r : (short)-1;
        if (r < k) kept[r] = (short)v;
    }
    __syncthreads();

    if (tid < 128) {
        int d = tid;
        int obase = b * k;
        float mx = -INFINITY, sm = 0.0f;
        for (int r = 0; r < k; r++) {
            int v = kept[r];
            float val = g_x[(size_t)(nbase + v) * HID + d] * s[v];
            g_xp[(size_t)(obase + r) * HID + d] = val;
            mx = fmaxf(mx, val);
            sm += val;
        }
        g_h[b*256 + d]       += mx;
        g_h[b*256 + 128 + d] += sm / (float)k;
    } else if (do_remap) {
        for (int e = b*EPG + (tid - 128); e < (b + 1)*EPG; e += 128) {
            int val = g_valid[e];
            int ns = -1, nd = -1;
            if (val) {
                ns = newloc[g_src[e] - nbase];
                nd = newloc[g_dst[e] - nbase];
            }
            int ok = val && (ns >= 0) && (nd >= 0);
            g_src[e]   = b*k + (ns >= 0 ? ns : 0);
            g_dst[e]   = b*k + (nd >= 0 ? nd : 0);
            g_valid[e] = ok;
        }
    }
}

// ---------------- final MLP head: 256 -> 128 -> 64 -> 1 (sigmoid) ------------
__global__ void mlp_kernel(const float* __restrict__ lw1, const float* __restrict__ lb1,
                           const float* __restrict__ lw2, const float* __restrict__ lb2,
                           const float* __restrict__ lw3, const float* __restrict__ lb3,
                           float* __restrict__ out) {
    __shared__ float hs[8][256];
    __shared__ float h1[8][128];
    __shared__ float h2[8][64];
    int tid = threadIdx.x;           // 128 threads
    int b0  = blockIdx.x * 8;

    for (int idx = tid; idx < 8*256; idx += 128) {
        int r = idx >> 8, c = idx & 255;
        hs[r][c] = g_h[(b0 + r)*256 + c];
    }
    __syncthreads();

    {
        float acc[8];
        float bbv = lb1[tid];
#pragma unroll
        for (int r = 0; r < 8; r++) acc[r] = bbv;
        for (int kk = 0; kk < 256; kk++) {
            float w = lw1[tid*256 + kk];
#pragma unroll
            for (int r = 0; r < 8; r++) acc[r] += hs[r][kk] * w;
        }
#pragma unroll
        for (int r = 0; r < 8; r++) h1[r][tid] = fmaxf(acc[r], 0.0f);
    }
    __syncthreads();

    if (tid < 64) {
        float acc[8];
        float bbv = lb2[tid];
#pragma unroll
        for (int r = 0; r < 8; r++) acc[r] = bbv;
        for (int kk = 0; kk < 128; kk++) {
            float w = lw2[tid*128 + kk];
#pragma unroll
            for (int r = 0; r < 8; r++) acc[r] += h1[r][kk] * w;
        }
#pragma unroll
        for (int r = 0; r < 8; r++) h2[r][tid] = fmaxf(acc[r], 0.0f);
    }
    __syncthreads();

    if (tid < 8) {
        float acc = lb3[0];
        for (int kk = 0; kk < 64; kk++) acc += h2[tid][kk] * lw3[kk];
        out[b0 + tid] = 1.0f / (1.0f + expf(-acc));
    }
}

// ---------------- launch ------------------------------------------------------
extern "C" void kernel_launch(void* const* d_in, const int* in_sizes, int n_in,
                              void* d_out, int out_size) {
    const int*   node_ids   = (const int*)d_in[0];
    const int*   edge_index = (const int*)d_in[1];
    const float* emb  = (const float*)d_in[3];
    const float* w1n  = (const float*)d_in[4];
    const float* w1r  = (const float*)d_in[5];
    const float* b1   = (const float*)d_in[6];
    const float* w2n  = (const float*)d_in[7];
    const float* w2r  = (const float*)d_in[8];
    const float* b2   = (const float*)d_in[9];
    const float* w3n  = (const float*)d_in[10];
    const float* w3r  = (const float*)d_in[11];
    const float* b3   = (const float*)d_in[12];
    const float* p1   = (const float*)d_in[13];
    const float* p2   = (const float*)d_in[14];
    const float* p3   = (const float*)d_in[15];
    const float* lw1  = (const float*)d_in[16];
    const float* lb1  = (const float*)d_in[17];
    const float* lw2  = (const float*)d_in[18];
    const float* lb2  = (const float*)d_in[19];
    const float* lw3  = (const float*)d_in[20];
    const float* lb3  = (const float*)d_in[21];
    float* out = (float*)d_out;

    init_kernel<<<(E_TOT + 255)/256, 256>>>(edge_index);
    gather_kernel<<<(N0*EMB + 255)/256, 256>>>(node_ids, emb);

    // level 1
    agg_kernel<EMB><<<B, 256>>>(NP);
    conv1_gemm<<<N0/128, 256>>>(w1n, w1r, b1, p1);
    topk_kernel<<<B, 256>>>(p1, NP, K1, 1);

    // level 2
    agg_kernel<HID><<<B, 256>>>(K1);
    sage_gemm<<<(B*K1)/128, 256>>>(w2n, w2r, b2, p2);
    topk_kernel<<<B, 256>>>(p2, K1, K2, 1);

    // level 3
    agg_kernel<HID><<<B, 256>>>(K2);
    sage_gemm<<<(B*K2)/128, 256>>>(w3n, w3r, b3, p3);
    topk_kernel<<<B, 256>>>(p3, K2, K3, 0);

    mlp_kernel<<<B/8, 128>>>(lw1, lb1, lw2, lb2, lw3, lb3, out);
}